// round 14
// baseline (speedup 1.0000x reference)
#include <cuda_runtime.h>

// Cost-volume construction (FINAL — locked configuration, session best):
//   out[0, c,      d, h, w] = imgl[0, c, h, w]                      (broadcast over d)
//   out[0, c + 32, d, h, w] = (w >= d) ? imgr[0, c, h, w - d] : 0
// Shapes: imgl/imgr (1, 32, 256, 480) f32, out (1, 64, 32, 256, 480) f32.
//
// Session conclusions (13 rounds of ncu evidence):
//  - Write-bandwidth-bound at the HBM3e write-stream ceiling: ~6.35 TB/s
//    (79-80% of 8 TB/s spec). DRAM traffic == output size (1.007 GB, the
//    theoretical minimum). ncu-internal dur 157.6-158.7 us == computed floor;
//    harness dur stable at 159.8-160.1 us across identical resubmissions.
//  - .cs streaming stores are load-bearing: default policy thrashes L2,
//    evicts the resident 31.5 MB inputs, +70 MB traffic => +14 us (R9).
//  - Thread-contiguous float4 is mandatory: wider per-thread footprints
//    half-fill 128B sectors (R4, ~2x cost) or raise traffic (R8 STG.256).
//  - Occupancy (41-89%), block size (256-1024), write ordering (sequential/
//    strided/interleaved), read-side load shape: all non-binding.
//    Interleaved L/R streams + block 512 measured best.

constexpr int C  = 32;
constexpr int D  = 32;
constexpr int H2 = 256;
constexpr int W2 = 480;
constexpr int W4 = W2 / 4;              // 120 float4 per row
constexpr int PLANE = H2 * W2;          // 122880 floats
constexpr int CH    = D * PLANE;        // 3,932,160 floats per out-channel
constexpr int DSPLIT = 8;               // disparities per thread
constexpr int NSPLIT = D / DSPLIT;      // 4

__global__ __launch_bounds__(512, 4) void cost_volume_kernel(
    const float* __restrict__ imgl,
    const float* __restrict__ imgr,
    float* __restrict__ out)
{
    int idx = blockIdx.x * blockDim.x + threadIdx.x;

    int w4 = idx % W4;
    int t  = idx / W4;
    int h  = t % H2;
    t /= H2;
    int c     = t % C;
    int split = t / C;                  // 0..3
    int w  = w4 * 4;
    int d0 = split * DSPLIT;

    // ---- Left operand: one float4, broadcast over DSPLIT disparities ----
    const float4 l = *reinterpret_cast<const float4*>(imgl + c * PLANE + h * W2 + w);

    // ---- Right operand: sliding 4-float register window ----
    const float* rrow = imgr + c * PLANE + h * W2;
    int s = w - d0;
    float4 r;
    r.x = (s     >= 0) ? rrow[s]     : 0.0f;
    r.y = (s + 1 >= 0) ? rrow[s + 1] : 0.0f;
    r.z = (s + 2 >= 0) ? rrow[s + 2] : 0.0f;
    r.w = (s + 3 >= 0) ? rrow[s + 3] : 0.0f;

    float* outL = out + c * CH       + d0 * PLANE + h * W2 + w;
    float* outR = out + (c + C) * CH + d0 * PLANE + h * W2 + w;

    // interleaved stores: both write streams active every iteration
    __stcs(reinterpret_cast<float4*>(outL), l);
    __stcs(reinterpret_cast<float4*>(outR), r);

#pragma unroll
    for (int i = 1; i < DSPLIT; ++i) {
        // window slides left by one element per disparity step
        r.w = r.z;
        r.z = r.y;
        r.y = r.x;
        int src = s - i;
        r.x = (src >= 0) ? __ldg(rrow + src) : 0.0f;
        __stcs(reinterpret_cast<float4*>(outL + i * PLANE), l);
        __stcs(reinterpret_cast<float4*>(outR + i * PLANE), r);
    }
}

extern "C" void kernel_launch(void* const* d_in, const int* in_sizes, int n_in,
                              void* d_out, int out_size)
{
    const float* imgl = (const float*)d_in[0];
    const float* imgr = (const float*)d_in[1];
    float* out = (float*)d_out;

    const int total = NSPLIT * C * H2 * W4;          // 3,932,160 threads
    const int block = 512;
    const int grid  = (total + block - 1) / block;   // 7680 blocks
    cost_volume_kernel<<<grid, block>>>(imgl, imgr, out);
}